// round 3
// baseline (speedup 1.0000x reference)
#include <cuda_runtime.h>

#define NPOS 9
#define NROWS 16384      // T*B = 512*32
#define D 128
#define TILE_ROWS 64
#define GRID_CTAS 264    // 256 + (9-1): provable max chunk count; all co-resident (2 CTAs/SM)
#define BUILD_CTAS 64

__device__ int g_count[NPOS];          // zero at entry; last exiting CTA re-zeros
__device__ int g_list[NPOS * NROWS];
__device__ int g_arrive;               // zero at entry; reset on exit
__device__ int g_exit;

// ---------------------------------------------------------------------------
// One fused kernel: build lists -> device-wide barrier -> plan -> grouped GEMM.
// Co-residency of all GRID_CTAS CTAs is guaranteed by __launch_bounds__(256,2)
// (<=128 regs) + 96KB smem (2 CTAs/SM, 296 slots >= 264), so the software
// barrier cannot deadlock.
// ---------------------------------------------------------------------------
__global__ void __launch_bounds__(256, 2)
fused_transfer(const void* __restrict__ pos_raw,
               const float* __restrict__ x,
               const float* __restrict__ table,
               float* __restrict__ out)
{
    extern __shared__ float smem[];
    float* Ms = smem;                  // [128][128] (GEMM phase)
    float* Xs = smem + D * D;          // [64][128]
    int*   s_i = (int*)smem;           // phase-1 overlay: [0..8]=cnt, [16..24]=base

    int tid = threadIdx.x;
    int cid = blockIdx.x;

    // ---------------- phase 1: group rows by clipped position --------------
    if (cid < BUILD_CTAS) {
        if (tid < NPOS) s_i[tid] = 0;
        // dtype probe: words [cid*256, cid*256+256) valid under int32 AND int64;
        // int64 => all odd words are zero high-words (values are 0..15).
        const int* pos32 = (const int*)pos_raw;
        int w = pos32[cid * 256 + tid];
        int found = (tid & 1) && (w != 0);
        int is32 = __syncthreads_or(found);   // doubles as the s_i init barrier

        int row = cid * 256 + tid;            // BUILD_CTAS*256 == NROWS exactly
        int p = is32 ? pos32[row] : (int)((const long long*)pos_raw)[row];
        int r = (p < 8) ? p : 8;
        int local = atomicAdd(&s_i[r], 1);
        __syncthreads();
        if (tid < NPOS) s_i[16 + tid] = atomicAdd(&g_count[tid], s_i[tid]);
        __syncthreads();
        g_list[r * NROWS + s_i[16 + r] + local] = row;
    }

    // ---------------- device-wide barrier ----------------------------------
    __syncthreads();
    if (tid == 0) {
        __threadfence();                       // publish g_list / g_count
        atomicAdd(&g_arrive, 1);
        while (*(volatile int*)&g_arrive < GRID_CTAS) { __nanosleep(64); }
    }
    __syncthreads();                           // release the other 255 threads

    // ---------------- plan: redundant per-thread prefix over 9 groups ------
    int myp = -1, chunk = 0, cnt = 0, total = 0;
    #pragma unroll
    for (int i = 0; i < NPOS; i++) {
        int c = __ldcg(&g_count[i]);
        int ch = (c + TILE_ROWS - 1) / TILE_ROWS;
        if (cid >= total && cid < total + ch) { myp = i; chunk = cid - total; cnt = c; }
        total += ch;
    }

    // ---------------- phase 2: per-group skinny GEMM ------------------------
    if (myp >= 0) {
        int row0 = chunk * TILE_ROWS;
        int nrows = cnt - row0;
        if (nrows > TILE_ROWS) nrows = TILE_ROWS;
        const int* list = g_list + myp * NROWS + row0;

        // load M = table[myp] (4096 float4, 16 per thread)
        {
            const float4* Mg = (const float4*)(table + myp * D * D);
            float4* Msv = (float4*)Ms;
            #pragma unroll
            for (int i = 0; i < 16; i++)
                Msv[tid + i * 256] = Mg[tid + i * 256];
        }
        // gather X rows (each row = 32 float4 contiguous in gmem)
        for (int i = tid; i < TILE_ROWS * 32; i += 256) {
            int rl = i >> 5;
            int c  = i & 31;
            if (rl < nrows) {
                int row = __ldcg(&list[rl]);
                ((float4*)Xs)[i] = ((const float4*)(x + row * D))[c];
            }
        }
        __syncthreads();

        int lane = tid & 31;        // cols [4*lane, 4*lane+3]
        int wrp  = tid >> 5;        // rows [8*wrp, 8*wrp+7]
        const float* Mp = Ms + lane * 4;
        const float* Xp = Xs + wrp * 8 * D;

        unsigned long long acc01[8], acc23[8];
        #pragma unroll
        for (int j = 0; j < 8; j++) { acc01[j] = 0ull; acc23[j] = 0ull; }

        for (int d = 0; d < D; d += 4) {
            float xr[8][4];
            #pragma unroll
            for (int j = 0; j < 8; j++) {
                float4 v = *(const float4*)(Xp + j * D + d);  // warp-uniform broadcast
                xr[j][0] = v.x; xr[j][1] = v.y; xr[j][2] = v.z; xr[j][3] = v.w;
            }
            #pragma unroll
            for (int dd = 0; dd < 4; dd++) {
                float4 m = *(const float4*)(Mp + (d + dd) * D); // 4-phase conflict-free
                unsigned long long m01, m23;
                asm("mov.b64 %0, {%1, %2};" : "=l"(m01) : "f"(m.x), "f"(m.y));
                asm("mov.b64 %0, {%1, %2};" : "=l"(m23) : "f"(m.z), "f"(m.w));
                #pragma unroll
                for (int j = 0; j < 8; j++) {
                    unsigned long long xx;
                    asm("mov.b64 %0, {%1, %1};" : "=l"(xx) : "f"(xr[j][dd]));
                    asm("fma.rn.f32x2 %0, %1, %2, %0;" : "+l"(acc01[j]) : "l"(m01), "l"(xx));
                    asm("fma.rn.f32x2 %0, %1, %2, %0;" : "+l"(acc23[j]) : "l"(m23), "l"(xx));
                }
            }
        }

        #pragma unroll
        for (int j = 0; j < 8; j++) {
            int rl = wrp * 8 + j;
            if (rl < nrows) {
                int row = __ldcg(&list[rl]);
                float a0, a1, a2, a3;
                asm("mov.b64 {%0, %1}, %2;" : "=f"(a0), "=f"(a1) : "l"(acc01[j]));
                asm("mov.b64 {%0, %1}, %2;" : "=f"(a2), "=f"(a3) : "l"(acc23[j]));
                float4 o; o.x = a0; o.y = a1; o.z = a2; o.w = a3;
                *(float4*)(out + row * D + lane * 4) = o;
            }
        }
    }

    // ---------------- exit: last CTA resets globals for the next replay ----
    __syncthreads();
    if (tid == 0) {
        int e = atomicAdd(&g_exit, 1);
        if (e == GRID_CTAS - 1) {
            #pragma unroll
            for (int i = 0; i < NPOS; i++) g_count[i] = 0;
            g_arrive = 0;
            g_exit = 0;
            __threadfence();
        }
    }
}

// ---------------------------------------------------------------------------
extern "C" void kernel_launch(void* const* d_in, const int* in_sizes, int n_in,
                              void* d_out, int out_size) {
    const void*  positions = d_in[0];                 // int32 or int64 [T,B] (auto-detected)
    const float* outputs   = (const float*)d_in[1];   // f32 [T,B,128]
    const float* table     = (const float*)d_in[2];   // f32 [9,128,128]
    float*       out       = (float*)d_out;           // f32 [T,B,128]
    (void)in_sizes; (void)n_in; (void)out_size;

    static const int SMEM_BYTES = (D * D + TILE_ROWS * D) * (int)sizeof(float); // 98304
    static cudaError_t attr_once = cudaFuncSetAttribute(
        fused_transfer, cudaFuncAttributeMaxDynamicSharedMemorySize, SMEM_BYTES);
    (void)attr_once;

    fused_transfer<<<GRID_CTAS, 256, SMEM_BYTES>>>(positions, outputs, table, out);
}